// round 14
// baseline (speedup 1.0000x reference)
#include <cuda_runtime.h>
#include <cuda_bf16.h>
#include <cstdint>

#define C 128
#define C4 32
#define MAX_N 100000
#define MAX_E 640000
#define MAXDEG 64
#define BM 32
#define GEMM_THREADS 256
#define A_SLAB 132                 // u32 per (k-chunk, mf) slab (128 + 4 pad)
#define A_U32 (16 * A_SLAB)        // 2112 u32 per buffer per hi/lo plane

// ---------------- scratch (device globals) -----------------------------------
__device__ float g_temb[C];
__device__ int   g_degi[MAX_N];
__device__ float g_dinv[MAX_N];
__device__ int   g_ell[(size_t)MAX_N * MAXDEG];
__device__ float g_bufA[(size_t)MAX_N * C];
__device__ float g_bufB[(size_t)MAX_N * C];
__device__ uint2 g_whi[2][4096];   // [mat][(ks*16+nf)*32+lane] = {b0,b1}
__device__ uint2 g_wlo[2][4096];

// ---------------- helpers ----------------------------------------------------
__device__ __forceinline__ unsigned pack_bf2(float a, float b) {
    __nv_bfloat162 v = __floats2bfloat162_rn(a, b);
    return *reinterpret_cast<unsigned*>(&v);
}
__device__ __forceinline__ float bf_hi(float x) {
    return __bfloat162float(__float2bfloat16(x));
}
__device__ __forceinline__ void mma16(float* c, unsigned a0, unsigned a1,
                                      unsigned a2, unsigned a3,
                                      unsigned b0, unsigned b1) {
    asm volatile(
        "mma.sync.aligned.m16n8k16.row.col.f32.bf16.bf16.f32 "
        "{%0,%1,%2,%3}, {%4,%5,%6,%7}, {%8,%9}, {%0,%1,%2,%3};\n"
        : "+f"(c[0]), "+f"(c[1]), "+f"(c[2]), "+f"(c[3])
        : "r"(a0), "r"(a1), "r"(a2), "r"(a3), "r"(b0), "r"(b1));
}

// ---------------- fused setup: W pack + temb + deg init ----------------------
__global__ void setup_kernel(const float* __restrict__ W1, const float* __restrict__ W2,
                             const float* __restrict__ t,
                             const float* __restrict__ tW1, const float* __restrict__ tb1,
                             const float* __restrict__ tW2, const float* __restrict__ tb2,
                             int N) {
    int b = blockIdx.x;
    if (b < 32) {
        int id = b * 256 + threadIdx.x;   // 0..8191
        int mat = id >> 12;
        int rem = id & 4095;
        int ks = rem >> 9, nf = (rem >> 5) & 15, lane = rem & 31;
        int k0 = ks * 16 + (lane & 3) * 2;
        int n = nf * 8 + (lane >> 2);
        const float* W = mat ? W2 : W1;
        float v00 = W[k0 * C + n];
        float v01 = W[(k0 + 1) * C + n];
        float v10 = W[(k0 + 8) * C + n];
        float v11 = W[(k0 + 9) * C + n];
        float h00 = bf_hi(v00), h01 = bf_hi(v01), h10 = bf_hi(v10), h11 = bf_hi(v11);
        int idx = (ks * 16 + nf) * 32 + lane;
        g_whi[mat][idx] = make_uint2(pack_bf2(h00, h01), pack_bf2(h10, h11));
        g_wlo[mat][idx] = make_uint2(pack_bf2(v00 - h00, v01 - h01),
                                     pack_bf2(v10 - h10, v11 - h11));
    } else if (b == 32) {
        __shared__ float hid[C];
        int j = threadIdx.x;
        if (j < C) {
            float tv = t[0];
            hid[j] = fmaxf(tv * tW1[j] + tb1[j], 0.0f);
        }
        __syncthreads();
        if (j < C) {
            float s = tb2[j];
#pragma unroll 8
            for (int i = 0; i < C; i++) s += hid[i] * tW2[i * C + j];
            g_temb[j] = s;
        }
    } else {
        int i = (b - 33) * 256 + threadIdx.x;
        if (i < N) g_degi[i] = 0;
    }
}

// ---------------- edge pass: degree count + ELL fill (one pass) --------------
__global__ void fill_ell_kernel(const int* __restrict__ src, const int* __restrict__ dst,
                                int E) {
    int e = blockIdx.x * blockDim.x + threadIdx.x;
    if (e >= E) return;
    int d = dst[e];
    int slot = atomicAdd(&g_degi[d], 1);
    if (slot < MAXDEG)
        g_ell[(size_t)d * MAXDEG + slot] = src[e];
}

// ---------------- dinv table -------------------------------------------------
__global__ void dinv_kernel(int N) {
    int i = blockIdx.x * blockDim.x + threadIdx.x;
    if (i < N) g_dinv[i] = rsqrtf((float)g_degi[i] + 1.0f);
}

// ---------------- GEMM: out[M,128] = dinv[row] * ((A (+temb)) @ W) -----------
__global__ void __launch_bounds__(GEMM_THREADS, 2)
gemm_bf16_kernel(const float* __restrict__ A,
                 const uint2* __restrict__ whi, const uint2* __restrict__ wlo,
                 float* __restrict__ out, int M, int ntiles, int add_temb) {
    __shared__ unsigned Ah[2][A_U32];
    __shared__ unsigned Al[2][A_U32];
    int tid = threadIdx.x, lane = tid & 31, warpN = tid >> 5;   // warpN 0..7

    uint2 wh[8][2], wl[8][2];
#pragma unroll
    for (int ks = 0; ks < 8; ks++)
#pragma unroll
        for (int j = 0; j < 2; j++) {
            int idx = (ks * 16 + warpN * 2 + j) * 32 + lane;
            wh[ks][j] = whi[idx];
            wl[ks][j] = wlo[idx];
        }

    int c4 = tid & 31;
    int ks_t = c4 >> 2;
    int khigh = (c4 >> 1) & 1;
    int kp0 = (c4 & 1) * 2;
    float4 tmb = make_float4(0.f, 0.f, 0.f, 0.f);
    if (add_temb) tmb = ((const float4*)g_temb)[c4];

    int G = gridDim.x;
    int tile = blockIdx.x;
    float4 pf[4];

#define LOADPF(T)                                                              \
    {                                                                          \
        _Pragma("unroll") for (int i = 0; i < 4; i++) {                        \
            int row = (T) * BM + warpN + i * 8;                                \
            pf[i] = (row < M) ? ((const float4*)A)[(size_t)row * C4 + c4]      \
                              : make_float4(0.f, 0.f, 0.f, 0.f);               \
        }                                                                      \
    }

#define STAGE(S)                                                               \
    {                                                                          \
        _Pragma("unroll") for (int i = 0; i < 4; i++) {                        \
            int r = warpN + i * 8;                                             \
            int rloc = r & 15, mf = r >> 4;                                    \
            float4 v = pf[i];                                                  \
            v.x += tmb.x; v.y += tmb.y; v.z += tmb.z; v.w += tmb.w;            \
            float hx = bf_hi(v.x), hy = bf_hi(v.y);                            \
            float hz = bf_hi(v.z), hw = bf_hi(v.w);                            \
            int slot = (ks_t * 2 + mf) * A_SLAB + ((rloc & 7) * 4 + kp0) * 4   \
                       + (rloc >> 3) + 2 * khigh;                              \
            Ah[S][slot]     = pack_bf2(hx, hy);                                \
            Ah[S][slot + 4] = pack_bf2(hz, hw);                                \
            Al[S][slot]     = pack_bf2(v.x - hx, v.y - hy);                    \
            Al[S][slot + 4] = pack_bf2(v.z - hz, v.w - hw);                    \
        }                                                                      \
    }

    if (tile < ntiles) {
        LOADPF(tile);
        STAGE(0);
        if (tile + G < ntiles) LOADPF(tile + G);
    }
    int s = 0;

    while (tile < ntiles) {
        __syncthreads();   // buf[s] staging complete across all warps
        if (tile + G < ntiles) {
            STAGE(s ^ 1);
            if (tile + 2 * G < ntiles) LOADPF(tile + 2 * G);
        }

        float acc[2][2][4];
#pragma unroll
        for (int mf = 0; mf < 2; mf++)
#pragma unroll
            for (int j = 0; j < 2; j++)
#pragma unroll
                for (int x = 0; x < 4; x++) acc[mf][j][x] = 0.f;

        const uint4* Ah4 = (const uint4*)Ah[s];
        const uint4* Al4 = (const uint4*)Al[s];
#pragma unroll
        for (int ks = 0; ks < 8; ks++) {
#pragma unroll
            for (int mf = 0; mf < 2; mf++) {
                uint4 ah = Ah4[(ks * 2 + mf) * (A_SLAB / 4) + lane];
                uint4 al = Al4[(ks * 2 + mf) * (A_SLAB / 4) + lane];
#pragma unroll
                for (int j = 0; j < 2; j++) {
                    mma16(acc[mf][j], ah.x, ah.y, ah.z, ah.w, wh[ks][j].x, wh[ks][j].y);
                    mma16(acc[mf][j], ah.x, ah.y, ah.z, ah.w, wl[ks][j].x, wl[ks][j].y);
                    mma16(acc[mf][j], al.x, al.y, al.z, al.w, wh[ks][j].x, wh[ks][j].y);
                }
            }
        }

        // epilogue: scale each output row by dinv[row], then store
        {
            int g = lane >> 2, cc = lane & 3;
#pragma unroll
            for (int mf = 0; mf < 2; mf++) {
                int row0 = tile * BM + mf * 16 + g;
                float sd0 = (row0 < M) ? g_dinv[row0] : 0.f;
                float sd1 = (row0 + 8 < M) ? g_dinv[row0 + 8] : 0.f;
#pragma unroll
                for (int j = 0; j < 2; j++) {
                    int col = (warpN * 2 + j) * 8 + cc * 2;
                    if (row0 < M)
                        *(float2*)(out + (size_t)row0 * C + col) =
                            make_float2(acc[mf][j][0] * sd0, acc[mf][j][1] * sd0);
                    if (row0 + 8 < M)
                        *(float2*)(out + (size_t)(row0 + 8) * C + col) =
                            make_float2(acc[mf][j][2] * sd1, acc[mf][j][3] * sd1);
                }
            }
        }
        s ^= 1;
        tile += G;
    }
#undef LOADPF
#undef STAGE
}

// ---------------- aggregation: predicated 8-wide unweighted gather-sum -------
// x rows are pre-scaled by dinv (in GEMM epilogue), so:
//   result = dinv_d * (sum_e x[s_e] + x[row]) + bias
__global__ void agg_kernel(const float* __restrict__ x, float* __restrict__ out,
                           const float* __restrict__ bias,
                           const float* __restrict__ lnw, const float* __restrict__ lnb,
                           int N, int do_ln) {
    int row = (blockIdx.x * blockDim.x + threadIdx.x) >> 5;
    int lane = threadIdx.x & 31;
    if (row >= N) return;
    int degr = g_degi[row];
    int deg = degr < MAXDEG ? degr : MAXDEG;
    float4 acc = ((const float4*)x)[(size_t)row * C4 + lane];   // self term (pre-scaled)

    const int4* ell4 = (const int4*)(g_ell + (size_t)row * MAXDEG);
    for (int i = 0; i < deg; i += 8) {
        int4 a = ell4[(i >> 2)];
        int4 b = ell4[(i >> 2) + 1];
        int si[8];
        float m[8];
        si[0] = a.x; si[1] = a.y; si[2] = a.z; si[3] = a.w;
        si[4] = b.x; si[5] = b.y; si[6] = b.z; si[7] = b.w;
#pragma unroll
        for (int k = 0; k < 8; k++) {
            bool valid = (i + k) < deg;
            m[k] = valid ? 1.0f : 0.0f;
            si[k] = valid ? si[k] : row;
        }
#pragma unroll
        for (int k = 0; k < 8; k++) {
            float4 v = ((const float4*)x)[(size_t)si[k] * C4 + lane];
            acc.x += m[k] * v.x;
            acc.y += m[k] * v.y;
            acc.z += m[k] * v.z;
            acc.w += m[k] * v.w;
        }
    }

    float dinv_d = g_dinv[row];
    float4 bb = ((const float4*)bias)[lane];
    acc.x = acc.x * dinv_d + bb.x;
    acc.y = acc.y * dinv_d + bb.y;
    acc.z = acc.z * dinv_d + bb.z;
    acc.w = acc.w * dinv_d + bb.w;

    if (do_ln) {
        float s = acc.x + acc.y + acc.z + acc.w;
#pragma unroll
        for (int o = 16; o > 0; o >>= 1) s += __shfl_xor_sync(0xFFFFFFFFu, s, o);
        float mu = s * (1.0f / 128.0f);
        float dx = acc.x - mu, dy = acc.y - mu, dz = acc.z - mu, dw = acc.w - mu;
        float sq = dx * dx + dy * dy + dz * dz + dw * dw;
#pragma unroll
        for (int o = 16; o > 0; o >>= 1) sq += __shfl_xor_sync(0xFFFFFFFFu, sq, o);
        float rstd = rsqrtf(sq * (1.0f / 128.0f) + 1e-5f);
        float4 w = ((const float4*)lnw)[lane];
        float4 lb = ((const float4*)lnb)[lane];
        acc.x = fmaxf(dx * rstd * w.x + lb.x, 0.0f);
        acc.y = fmaxf(dy * rstd * w.y + lb.y, 0.0f);
        acc.z = fmaxf(dz * rstd * w.z + lb.z, 0.0f);
        acc.w = fmaxf(dw * rstd * w.w + lb.w, 0.0f);
    }
    ((float4*)out)[(size_t)row * C4 + lane] = acc;
}

// ---------------- launcher ---------------------------------------------------
extern "C" void kernel_launch(void* const* d_in, const int* in_sizes, int n_in,
                              void* d_out, int out_size) {
    const float* h_noisy = (const float*)d_in[0];
    const int*   edge    = (const int*)  d_in[1];
    const float* t       = (const float*)d_in[2];
    const float* tW1     = (const float*)d_in[3];
    const float* tb1     = (const float*)d_in[4];
    const float* tW2     = (const float*)d_in[5];
    const float* tb2     = (const float*)d_in[6];
    const float* W1      = (const float*)d_in[7];
    const float* b1      = (const float*)d_in[8];
    const float* W2      = (const float*)d_in[9];
    const float* b2      = (const float*)d_in[10];
    const float* ln_w    = (const float*)d_in[11];
    const float* ln_b    = (const float*)d_in[12];
    float* out = (float*)d_out;

    int N = in_sizes[0] / C;
    int E = in_sizes[1] / 2;
    const int* src = edge;
    const int* dst = edge + E;

    float *bufA, *bufB;
    uint2 *whi, *wlo;
    cudaGetSymbolAddress((void**)&bufA, g_bufA);
    cudaGetSymbolAddress((void**)&bufB, g_bufB);
    cudaGetSymbolAddress((void**)&whi, g_whi);
    cudaGetSymbolAddress((void**)&wlo, g_wlo);

    int nblkN = (N + 255) / 256;       // 391
    int nblkE = (E + 255) / 256;
    int ntiles = (N + BM - 1) / BM;    // 3125
    int row_blocks = (N * 32 + 255) / 256;

    // 1. fused setup (W pack + temb + deg init)
    setup_kernel<<<33 + nblkN, 256>>>(W1, W2, t, tW1, tb1, tW2, tb2, N);
    // 2. edge pass: degrees + ELL adjacency (one pass)
    fill_ell_kernel<<<nblkE, 256>>>(src, dst, E);
    // 3. dinv table (row-coalesced use only)
    dinv_kernel<<<nblkN, 256>>>(N);
    // 4. gemm1 (profiled slot): dinv * ((h + temb) @ W1) -> bufA
    gemm_bf16_kernel<<<296, GEMM_THREADS>>>(h_noisy, whi, wlo, bufA, N, ntiles, 1);
    // 5. aggregate + LN + ReLU -> bufB
    agg_kernel<<<row_blocks, 256>>>(bufA, bufB, b1, ln_w, ln_b, N, 1);
    // 6. gemm2: dinv * (bufB @ W2) -> bufA
    gemm_bf16_kernel<<<296, GEMM_THREADS>>>(bufB, whi + 4096, wlo + 4096, bufA, N, ntiles, 0);
    // 7. aggregate -> out
    agg_kernel<<<row_blocks, 256>>>(bufA, out, b2, nullptr, nullptr, N, 0);
}

// round 15
// speedup vs baseline: 1.0500x; 1.0500x over previous
#include <cuda_runtime.h>
#include <cuda_bf16.h>
#include <cuda_fp16.h>
#include <cstdint>

#define C 128
#define C4 32
#define MAX_N 100000
#define MAX_E 640000
#define MAXDEG 64
#define BM 32
#define GEMM_THREADS 256
#define A_SLAB 132                 // u32 per (k-chunk, mf) slab (128 + 4 pad)
#define A_U32 (16 * A_SLAB)        // 2112 u32 per buffer per hi/lo plane

// ---------------- scratch (device globals) -----------------------------------
__device__ float g_temb[C];
__device__ int   g_degi[MAX_N];
__device__ float g_dinv[MAX_N];
__device__ int   g_ell[(size_t)MAX_N * MAXDEG];
__device__ __half2 g_buf16[(size_t)MAX_N * 64];   // fp16 gemm output (pre-scaled)
__device__ float g_bufB[(size_t)MAX_N * C];       // fp32 agg1 output
__device__ uint2 g_whi[2][4096];   // [mat][(ks*16+nf)*32+lane] = {b0,b1}
__device__ uint2 g_wlo[2][4096];

// ---------------- helpers ----------------------------------------------------
__device__ __forceinline__ unsigned pack_bf2(float a, float b) {
    __nv_bfloat162 v = __floats2bfloat162_rn(a, b);
    return *reinterpret_cast<unsigned*>(&v);
}
__device__ __forceinline__ float bf_hi(float x) {
    return __bfloat162float(__float2bfloat16(x));
}
__device__ __forceinline__ float4 h4_to_f4(uint2 u) {
    __half2 a = *reinterpret_cast<__half2*>(&u.x);
    __half2 b = *reinterpret_cast<__half2*>(&u.y);
    float2 fa = __half22float2(a), fb = __half22float2(b);
    return make_float4(fa.x, fa.y, fb.x, fb.y);
}
__device__ __forceinline__ void mma16(float* c, unsigned a0, unsigned a1,
                                      unsigned a2, unsigned a3,
                                      unsigned b0, unsigned b1) {
    asm volatile(
        "mma.sync.aligned.m16n8k16.row.col.f32.bf16.bf16.f32 "
        "{%0,%1,%2,%3}, {%4,%5,%6,%7}, {%8,%9}, {%0,%1,%2,%3};\n"
        : "+f"(c[0]), "+f"(c[1]), "+f"(c[2]), "+f"(c[3])
        : "r"(a0), "r"(a1), "r"(a2), "r"(a3), "r"(b0), "r"(b1));
}

// ---------------- fused setup: W pack + temb + deg init ----------------------
__global__ void setup_kernel(const float* __restrict__ W1, const float* __restrict__ W2,
                             const float* __restrict__ t,
                             const float* __restrict__ tW1, const float* __restrict__ tb1,
                             const float* __restrict__ tW2, const float* __restrict__ tb2,
                             int N) {
    int b = blockIdx.x;
    if (b < 32) {
        int id = b * 256 + threadIdx.x;   // 0..8191
        int mat = id >> 12;
        int rem = id & 4095;
        int ks = rem >> 9, nf = (rem >> 5) & 15, lane = rem & 31;
        int k0 = ks * 16 + (lane & 3) * 2;
        int n = nf * 8 + (lane >> 2);
        const float* W = mat ? W2 : W1;
        float v00 = W[k0 * C + n];
        float v01 = W[(k0 + 1) * C + n];
        float v10 = W[(k0 + 8) * C + n];
        float v11 = W[(k0 + 9) * C + n];
        float h00 = bf_hi(v00), h01 = bf_hi(v01), h10 = bf_hi(v10), h11 = bf_hi(v11);
        int idx = (ks * 16 + nf) * 32 + lane;
        g_whi[mat][idx] = make_uint2(pack_bf2(h00, h01), pack_bf2(h10, h11));
        g_wlo[mat][idx] = make_uint2(pack_bf2(v00 - h00, v01 - h01),
                                     pack_bf2(v10 - h10, v11 - h11));
    } else if (b == 32) {
        __shared__ float hid[C];
        int j = threadIdx.x;
        if (j < C) {
            float tv = t[0];
            hid[j] = fmaxf(tv * tW1[j] + tb1[j], 0.0f);
        }
        __syncthreads();
        if (j < C) {
            float s = tb2[j];
#pragma unroll 8
            for (int i = 0; i < C; i++) s += hid[i] * tW2[i * C + j];
            g_temb[j] = s;
        }
    } else {
        int i = (b - 33) * 256 + threadIdx.x;
        if (i < N) g_degi[i] = 0;
    }
}

// ---------------- edge pass: degree count + ELL fill (one pass) --------------
__global__ void fill_ell_kernel(const int* __restrict__ src, const int* __restrict__ dst,
                                int E) {
    int e = blockIdx.x * blockDim.x + threadIdx.x;
    if (e >= E) return;
    int d = dst[e];
    int slot = atomicAdd(&g_degi[d], 1);
    if (slot < MAXDEG)
        g_ell[(size_t)d * MAXDEG + slot] = src[e];
}

// ---------------- dinv table -------------------------------------------------
__global__ void dinv_kernel(int N) {
    int i = blockIdx.x * blockDim.x + threadIdx.x;
    if (i < N) g_dinv[i] = rsqrtf((float)g_degi[i] + 1.0f);
}

// ---------------- GEMM: out16[M,128] = fp16( dinv[row] * ((A (+temb)) @ W) ) -
__global__ void __launch_bounds__(GEMM_THREADS, 2)
gemm_bf16_kernel(const float* __restrict__ A,
                 const uint2* __restrict__ whi, const uint2* __restrict__ wlo,
                 __half2* __restrict__ out16, int M, int ntiles, int add_temb) {
    __shared__ unsigned Ah[2][A_U32];
    __shared__ unsigned Al[2][A_U32];
    int tid = threadIdx.x, lane = tid & 31, warpN = tid >> 5;   // warpN 0..7

    uint2 wh[8][2], wl[8][2];
#pragma unroll
    for (int ks = 0; ks < 8; ks++)
#pragma unroll
        for (int j = 0; j < 2; j++) {
            int idx = (ks * 16 + warpN * 2 + j) * 32 + lane;
            wh[ks][j] = whi[idx];
            wl[ks][j] = wlo[idx];
        }

    int c4 = tid & 31;
    int ks_t = c4 >> 2;
    int khigh = (c4 >> 1) & 1;
    int kp0 = (c4 & 1) * 2;
    float4 tmb = make_float4(0.f, 0.f, 0.f, 0.f);
    if (add_temb) tmb = ((const float4*)g_temb)[c4];

    int G = gridDim.x;
    int tile = blockIdx.x;
    float4 pf[4];

#define LOADPF(T)                                                              \
    {                                                                          \
        _Pragma("unroll") for (int i = 0; i < 4; i++) {                        \
            int row = (T) * BM + warpN + i * 8;                                \
            pf[i] = (row < M) ? ((const float4*)A)[(size_t)row * C4 + c4]      \
                              : make_float4(0.f, 0.f, 0.f, 0.f);               \
        }                                                                      \
    }

#define STAGE(S)                                                               \
    {                                                                          \
        _Pragma("unroll") for (int i = 0; i < 4; i++) {                        \
            int r = warpN + i * 8;                                             \
            int rloc = r & 15, mf = r >> 4;                                    \
            float4 v = pf[i];                                                  \
            v.x += tmb.x; v.y += tmb.y; v.z += tmb.z; v.w += tmb.w;            \
            float hx = bf_hi(v.x), hy = bf_hi(v.y);                            \
            float hz = bf_hi(v.z), hw = bf_hi(v.w);                            \
            int slot = (ks_t * 2 + mf) * A_SLAB + ((rloc & 7) * 4 + kp0) * 4   \
                       + (rloc >> 3) + 2 * khigh;                              \
            Ah[S][slot]     = pack_bf2(hx, hy);                                \
            Ah[S][slot + 4] = pack_bf2(hz, hw);                                \
            Al[S][slot]     = pack_bf2(v.x - hx, v.y - hy);                    \
            Al[S][slot + 4] = pack_bf2(v.z - hz, v.w - hw);                    \
        }                                                                      \
    }

    if (tile < ntiles) {
        LOADPF(tile);
        STAGE(0);
        if (tile + G < ntiles) LOADPF(tile + G);
    }
    int s = 0;

    while (tile < ntiles) {
        __syncthreads();   // buf[s] staging complete across all warps
        if (tile + G < ntiles) {
            STAGE(s ^ 1);
            if (tile + 2 * G < ntiles) LOADPF(tile + 2 * G);
        }

        float acc[2][2][4];
#pragma unroll
        for (int mf = 0; mf < 2; mf++)
#pragma unroll
            for (int j = 0; j < 2; j++)
#pragma unroll
                for (int x = 0; x < 4; x++) acc[mf][j][x] = 0.f;

        const uint4* Ah4 = (const uint4*)Ah[s];
        const uint4* Al4 = (const uint4*)Al[s];
#pragma unroll
        for (int ks = 0; ks < 8; ks++) {
#pragma unroll
            for (int mf = 0; mf < 2; mf++) {
                uint4 ah = Ah4[(ks * 2 + mf) * (A_SLAB / 4) + lane];
                uint4 al = Al4[(ks * 2 + mf) * (A_SLAB / 4) + lane];
#pragma unroll
                for (int j = 0; j < 2; j++) {
                    mma16(acc[mf][j], ah.x, ah.y, ah.z, ah.w, wh[ks][j].x, wh[ks][j].y);
                    mma16(acc[mf][j], ah.x, ah.y, ah.z, ah.w, wl[ks][j].x, wl[ks][j].y);
                    mma16(acc[mf][j], al.x, al.y, al.z, al.w, wh[ks][j].x, wh[ks][j].y);
                }
            }
        }

        // epilogue: scale by dinv[row], convert to fp16, store half2
        {
            int g = lane >> 2, cc = lane & 3;
#pragma unroll
            for (int mf = 0; mf < 2; mf++) {
                int row0 = tile * BM + mf * 16 + g;
                float sd0 = (row0 < M) ? g_dinv[row0] : 0.f;
                float sd1 = (row0 + 8 < M) ? g_dinv[row0 + 8] : 0.f;
#pragma unroll
                for (int j = 0; j < 2; j++) {
                    int col2 = ((warpN * 2 + j) * 8 + cc * 2) >> 1;  // half2 index
                    if (row0 < M)
                        out16[(size_t)row0 * 64 + col2] =
                            __floats2half2_rn(acc[mf][j][0] * sd0, acc[mf][j][1] * sd0);
                    if (row0 + 8 < M)
                        out16[(size_t)(row0 + 8) * 64 + col2] =
                            __floats2half2_rn(acc[mf][j][2] * sd1, acc[mf][j][3] * sd1);
                }
            }
        }
        s ^= 1;
        tile += G;
    }
#undef LOADPF
#undef STAGE
}

// ---------------- aggregation: fp16 gathers, fp32 accumulate -----------------
// x16 rows are pre-scaled by dinv, so: result = dinv_d*(sum x16[s] + x16[row]) + bias
__global__ void agg_kernel(const __half2* __restrict__ x16, float* __restrict__ out,
                           const float* __restrict__ bias,
                           const float* __restrict__ lnw, const float* __restrict__ lnb,
                           int N, int do_ln) {
    int row = (blockIdx.x * blockDim.x + threadIdx.x) >> 5;
    int lane = threadIdx.x & 31;
    if (row >= N) return;
    int degr = g_degi[row];
    int deg = degr < MAXDEG ? degr : MAXDEG;
    const uint2* xr = (const uint2*)x16;   // [s*32 + lane] = 4 halves (cols lane*4..+3)

    float4 acc = h4_to_f4(xr[(size_t)row * 32 + lane]);   // self term

    const int* ell = g_ell + (size_t)row * MAXDEG;
    int i = 0;
    for (; i + 4 <= deg; i += 4) {
        int s0 = ell[i], s1 = ell[i + 1], s2 = ell[i + 2], s3 = ell[i + 3];
        float4 v0 = h4_to_f4(xr[(size_t)s0 * 32 + lane]);
        float4 v1 = h4_to_f4(xr[(size_t)s1 * 32 + lane]);
        float4 v2 = h4_to_f4(xr[(size_t)s2 * 32 + lane]);
        float4 v3 = h4_to_f4(xr[(size_t)s3 * 32 + lane]);
        acc.x += v0.x + v1.x + v2.x + v3.x;
        acc.y += v0.y + v1.y + v2.y + v3.y;
        acc.z += v0.z + v1.z + v2.z + v3.z;
        acc.w += v0.w + v1.w + v2.w + v3.w;
    }
    for (; i < deg; i++) {
        int s0 = ell[i];
        float4 v0 = h4_to_f4(xr[(size_t)s0 * 32 + lane]);
        acc.x += v0.x;
        acc.y += v0.y;
        acc.z += v0.z;
        acc.w += v0.w;
    }

    float dinv_d = g_dinv[row];
    float4 bb = ((const float4*)bias)[lane];
    acc.x = acc.x * dinv_d + bb.x;
    acc.y = acc.y * dinv_d + bb.y;
    acc.z = acc.z * dinv_d + bb.z;
    acc.w = acc.w * dinv_d + bb.w;

    if (do_ln) {
        float s = acc.x + acc.y + acc.z + acc.w;
#pragma unroll
        for (int o = 16; o > 0; o >>= 1) s += __shfl_xor_sync(0xFFFFFFFFu, s, o);
        float mu = s * (1.0f / 128.0f);
        float dx = acc.x - mu, dy = acc.y - mu, dz = acc.z - mu, dw = acc.w - mu;
        float sq = dx * dx + dy * dy + dz * dz + dw * dw;
#pragma unroll
        for (int o = 16; o > 0; o >>= 1) sq += __shfl_xor_sync(0xFFFFFFFFu, sq, o);
        float rstd = rsqrtf(sq * (1.0f / 128.0f) + 1e-5f);
        float4 w = ((const float4*)lnw)[lane];
        float4 lb = ((const float4*)lnb)[lane];
        acc.x = fmaxf(dx * rstd * w.x + lb.x, 0.0f);
        acc.y = fmaxf(dy * rstd * w.y + lb.y, 0.0f);
        acc.z = fmaxf(dz * rstd * w.z + lb.z, 0.0f);
        acc.w = fmaxf(dw * rstd * w.w + lb.w, 0.0f);
    }
    ((float4*)out)[(size_t)row * C4 + lane] = acc;
}

// ---------------- launcher ---------------------------------------------------
extern "C" void kernel_launch(void* const* d_in, const int* in_sizes, int n_in,
                              void* d_out, int out_size) {
    const float* h_noisy = (const float*)d_in[0];
    const int*   edge    = (const int*)  d_in[1];
    const float* t       = (const float*)d_in[2];
    const float* tW1     = (const float*)d_in[3];
    const float* tb1     = (const float*)d_in[4];
    const float* tW2     = (const float*)d_in[5];
    const float* tb2     = (const float*)d_in[6];
    const float* W1      = (const float*)d_in[7];
    const float* b1      = (const float*)d_in[8];
    const float* W2      = (const float*)d_in[9];
    const float* b2      = (const float*)d_in[10];
    const float* ln_w    = (const float*)d_in[11];
    const float* ln_b    = (const float*)d_in[12];
    float* out = (float*)d_out;

    int N = in_sizes[0] / C;
    int E = in_sizes[1] / 2;
    const int* src = edge;
    const int* dst = edge + E;

    float* bufB;
    __half2* buf16;
    uint2 *whi, *wlo;
    cudaGetSymbolAddress((void**)&bufB, g_bufB);
    cudaGetSymbolAddress((void**)&buf16, g_buf16);
    cudaGetSymbolAddress((void**)&whi, g_whi);
    cudaGetSymbolAddress((void**)&wlo, g_wlo);

    int nblkN = (N + 255) / 256;       // 391
    int nblkE = (E + 255) / 256;
    int ntiles = (N + BM - 1) / BM;    // 3125
    int row_blocks = (N * 32 + 255) / 256;

    // 1. fused setup (W pack + temb + deg init)
    setup_kernel<<<33 + nblkN, 256>>>(W1, W2, t, tW1, tb1, tW2, tb2, N);
    // 2. edge pass: degrees + ELL adjacency (one pass)
    fill_ell_kernel<<<nblkE, 256>>>(src, dst, E);
    // 3. dinv table
    dinv_kernel<<<nblkN, 256>>>(N);
    // 4. gemm1 (profiled slot): fp16( dinv * ((h + temb) @ W1) ) -> buf16
    gemm_bf16_kernel<<<296, GEMM_THREADS>>>(h_noisy, whi, wlo, buf16, N, ntiles, 1);
    // 5. aggregate + LN + ReLU -> bufB (fp32)
    agg_kernel<<<row_blocks, 256>>>(buf16, bufB, b1, ln_w, ln_b, N, 1);
    // 6. gemm2: fp16( dinv * (bufB @ W2) ) -> buf16
    gemm_bf16_kernel<<<296, GEMM_THREADS>>>(bufB, whi + 4096, wlo + 4096, buf16, N, ntiles, 0);
    // 7. aggregate -> out (fp32)
    agg_kernel<<<row_blocks, 256>>>(buf16, out, b2, nullptr, nullptr, N, 0);
}

// round 16
// speedup vs baseline: 1.0937x; 1.0416x over previous
#include <cuda_runtime.h>
#include <cuda_bf16.h>
#include <cuda_fp16.h>
#include <cstdint>

#define C 128
#define C4 32
#define MAX_N 100000
#define MAX_E 640000
#define MAXDEG 64
#define BM 32
#define GEMM_THREADS 256
#define A_SLAB 132                 // u32 per (k-chunk, mf) slab (128 + 4 pad)
#define A_U32 (16 * A_SLAB)        // 2112 u32 per buffer per hi/lo plane

// ---------------- scratch (device globals) -----------------------------------
__device__ float g_temb[C];
__device__ int   g_degi[MAX_N];
__device__ float g_dinv[MAX_N];
__device__ int   g_ell[(size_t)MAX_N * MAXDEG];
__device__ __half2 g_buf16a[(size_t)MAX_N * 64];  // gemm outputs (pre-scaled)
__device__ __half2 g_buf16b[(size_t)MAX_N * 64];  // agg1 output (fp16)
__device__ uint2 g_whi[2][4096];   // [mat][(ks*16+nf)*32+lane] = {b0,b1}
__device__ uint2 g_wlo[2][4096];

// ---------------- helpers ----------------------------------------------------
__device__ __forceinline__ unsigned pack_bf2(float a, float b) {
    __nv_bfloat162 v = __floats2bfloat162_rn(a, b);
    return *reinterpret_cast<unsigned*>(&v);
}
__device__ __forceinline__ float bf_hi(float x) {
    return __bfloat162float(__float2bfloat16(x));
}
__device__ __forceinline__ float4 h4_to_f4(uint2 u) {
    __half2 a = *reinterpret_cast<__half2*>(&u.x);
    __half2 b = *reinterpret_cast<__half2*>(&u.y);
    float2 fa = __half22float2(a), fb = __half22float2(b);
    return make_float4(fa.x, fa.y, fb.x, fb.y);
}
__device__ __forceinline__ void mma16(float* c, unsigned a0, unsigned a1,
                                      unsigned a2, unsigned a3,
                                      unsigned b0, unsigned b1) {
    asm volatile(
        "mma.sync.aligned.m16n8k16.row.col.f32.bf16.bf16.f32 "
        "{%0,%1,%2,%3}, {%4,%5,%6,%7}, {%8,%9}, {%0,%1,%2,%3};\n"
        : "+f"(c[0]), "+f"(c[1]), "+f"(c[2]), "+f"(c[3])
        : "r"(a0), "r"(a1), "r"(a2), "r"(a3), "r"(b0), "r"(b1));
}

// ---------------- fused setup: W pack + temb + deg init ----------------------
__global__ void setup_kernel(const float* __restrict__ W1, const float* __restrict__ W2,
                             const float* __restrict__ t,
                             const float* __restrict__ tW1, const float* __restrict__ tb1,
                             const float* __restrict__ tW2, const float* __restrict__ tb2,
                             int N) {
    int b = blockIdx.x;
    if (b < 32) {
        int id = b * 256 + threadIdx.x;   // 0..8191
        int mat = id >> 12;
        int rem = id & 4095;
        int ks = rem >> 9, nf = (rem >> 5) & 15, lane = rem & 31;
        int k0 = ks * 16 + (lane & 3) * 2;
        int n = nf * 8 + (lane >> 2);
        const float* W = mat ? W2 : W1;
        float v00 = W[k0 * C + n];
        float v01 = W[(k0 + 1) * C + n];
        float v10 = W[(k0 + 8) * C + n];
        float v11 = W[(k0 + 9) * C + n];
        float h00 = bf_hi(v00), h01 = bf_hi(v01), h10 = bf_hi(v10), h11 = bf_hi(v11);
        int idx = (ks * 16 + nf) * 32 + lane;
        g_whi[mat][idx] = make_uint2(pack_bf2(h00, h01), pack_bf2(h10, h11));
        g_wlo[mat][idx] = make_uint2(pack_bf2(v00 - h00, v01 - h01),
                                     pack_bf2(v10 - h10, v11 - h11));
    } else if (b == 32) {
        __shared__ float hid[C];
        int j = threadIdx.x;
        if (j < C) {
            float tv = t[0];
            hid[j] = fmaxf(tv * tW1[j] + tb1[j], 0.0f);
        }
        __syncthreads();
        if (j < C) {
            float s = tb2[j];
#pragma unroll 8
            for (int i = 0; i < C; i++) s += hid[i] * tW2[i * C + j];
            g_temb[j] = s;
        }
    } else {
        int i = (b - 33) * 256 + threadIdx.x;
        if (i < N) g_degi[i] = 0;
    }
}

// ---------------- edge pass: degree count + ELL fill (one pass) --------------
__global__ void fill_ell_kernel(const int* __restrict__ src, const int* __restrict__ dst,
                                int E) {
    int e = blockIdx.x * blockDim.x + threadIdx.x;
    if (e >= E) return;
    int d = dst[e];
    int slot = atomicAdd(&g_degi[d], 1);
    if (slot < MAXDEG)
        g_ell[(size_t)d * MAXDEG + slot] = src[e];
}

// ---------------- dinv table -------------------------------------------------
__global__ void dinv_kernel(int N) {
    int i = blockIdx.x * blockDim.x + threadIdx.x;
    if (i < N) g_dinv[i] = rsqrtf((float)g_degi[i] + 1.0f);
}

// ---------------- GEMM: out16 = fp16( dinv[row] * ((A (+temb)) @ W) ) --------
// A is fp32 (a_fp16=0, optional temb add) or fp16 half2 rows (a_fp16=1).
// fp16 -> bf16 hi/lo split is exact (11 sig bits <= 8+8).
__global__ void __launch_bounds__(GEMM_THREADS, 2)
gemm_bf16_kernel(const void* __restrict__ Ain,
                 const uint2* __restrict__ whi, const uint2* __restrict__ wlo,
                 __half2* __restrict__ out16, int M, int ntiles,
                 int add_temb, int a_fp16) {
    __shared__ unsigned Ah[2][A_U32];
    __shared__ unsigned Al[2][A_U32];
    int tid = threadIdx.x, lane = tid & 31, warpN = tid >> 5;   // warpN 0..7

    uint2 wh[8][2], wl[8][2];
#pragma unroll
    for (int ks = 0; ks < 8; ks++)
#pragma unroll
        for (int j = 0; j < 2; j++) {
            int idx = (ks * 16 + warpN * 2 + j) * 32 + lane;
            wh[ks][j] = whi[idx];
            wl[ks][j] = wlo[idx];
        }

    int c4 = tid & 31;
    int ks_t = c4 >> 2;
    int khigh = (c4 >> 1) & 1;
    int kp0 = (c4 & 1) * 2;
    float4 tmb = make_float4(0.f, 0.f, 0.f, 0.f);
    if (add_temb) tmb = ((const float4*)g_temb)[c4];

    const float4* Af = (const float4*)Ain;
    const uint2* Ah16 = (const uint2*)Ain;

    int G = gridDim.x;
    int tile = blockIdx.x;
    float4 pf[4];

#define LOADPF(T)                                                              \
    {                                                                          \
        _Pragma("unroll") for (int i = 0; i < 4; i++) {                        \
            int row = (T) * BM + warpN + i * 8;                                \
            if (row < M) {                                                     \
                pf[i] = a_fp16 ? h4_to_f4(Ah16[(size_t)row * 32 + c4])         \
                               : Af[(size_t)row * C4 + c4];                    \
            } else {                                                           \
                pf[i] = make_float4(0.f, 0.f, 0.f, 0.f);                       \
            }                                                                  \
        }                                                                      \
    }

#define STAGE(S)                                                               \
    {                                                                          \
        _Pragma("unroll") for (int i = 0; i < 4; i++) {                        \
            int r = warpN + i * 8;                                             \
            int rloc = r & 15, mf = r >> 4;                                    \
            float4 v = pf[i];                                                  \
            v.x += tmb.x; v.y += tmb.y; v.z += tmb.z; v.w += tmb.w;            \
            float hx = bf_hi(v.x), hy = bf_hi(v.y);                            \
            float hz = bf_hi(v.z), hw = bf_hi(v.w);                            \
            int slot = (ks_t * 2 + mf) * A_SLAB + ((rloc & 7) * 4 + kp0) * 4   \
                       + (rloc >> 3) + 2 * khigh;                              \
            Ah[S][slot]     = pack_bf2(hx, hy);                                \
            Ah[S][slot + 4] = pack_bf2(hz, hw);                                \
            Al[S][slot]     = pack_bf2(v.x - hx, v.y - hy);                    \
            Al[S][slot + 4] = pack_bf2(v.z - hz, v.w - hw);                    \
        }                                                                      \
    }

    if (tile < ntiles) {
        LOADPF(tile);
        STAGE(0);
        if (tile + G < ntiles) LOADPF(tile + G);
    }
    int s = 0;

    while (tile < ntiles) {
        __syncthreads();   // buf[s] staging complete across all warps
        if (tile + G < ntiles) {
            STAGE(s ^ 1);
            if (tile + 2 * G < ntiles) LOADPF(tile + 2 * G);
        }

        // hoist epilogue dinv loads so they're in flight during the MMA loop
        int eg = lane >> 2, ecc = lane & 3;
        float sd[2][2];
#pragma unroll
        for (int mf = 0; mf < 2; mf++) {
            int row0 = tile * BM + mf * 16 + eg;
            sd[mf][0] = (row0 < M) ? g_dinv[row0] : 0.f;
            sd[mf][1] = (row0 + 8 < M) ? g_dinv[row0 + 8] : 0.f;
        }

        float acc[2][2][4];
#pragma unroll
        for (int mf = 0; mf < 2; mf++)
#pragma unroll
            for (int j = 0; j < 2; j++)
#pragma unroll
                for (int x = 0; x < 4; x++) acc[mf][j][x] = 0.f;

        const uint4* Ah4 = (const uint4*)Ah[s];
        const uint4* Al4 = (const uint4*)Al[s];
#pragma unroll
        for (int ks = 0; ks < 8; ks++) {
#pragma unroll
            for (int mf = 0; mf < 2; mf++) {
                uint4 ah = Ah4[(ks * 2 + mf) * (A_SLAB / 4) + lane];
                uint4 al = Al4[(ks * 2 + mf) * (A_SLAB / 4) + lane];
#pragma unroll
                for (int j = 0; j < 2; j++) {
                    mma16(acc[mf][j], ah.x, ah.y, ah.z, ah.w, wh[ks][j].x, wh[ks][j].y);
                    mma16(acc[mf][j], ah.x, ah.y, ah.z, ah.w, wl[ks][j].x, wl[ks][j].y);
                    mma16(acc[mf][j], al.x, al.y, al.z, al.w, wh[ks][j].x, wh[ks][j].y);
                }
            }
        }

        // epilogue: scale by pre-loaded dinv, convert to fp16, store half2
        {
#pragma unroll
            for (int mf = 0; mf < 2; mf++) {
                int row0 = tile * BM + mf * 16 + eg;
#pragma unroll
                for (int j = 0; j < 2; j++) {
                    int col2 = ((warpN * 2 + j) * 8 + ecc * 2) >> 1;  // half2 index
                    if (row0 < M)
                        out16[(size_t)row0 * 64 + col2] =
                            __floats2half2_rn(acc[mf][j][0] * sd[mf][0],
                                              acc[mf][j][1] * sd[mf][0]);
                    if (row0 + 8 < M)
                        out16[(size_t)(row0 + 8) * 64 + col2] =
                            __floats2half2_rn(acc[mf][j][2] * sd[mf][1],
                                              acc[mf][j][3] * sd[mf][1]);
                }
            }
        }
        s ^= 1;
        tile += G;
    }
#undef LOADPF
#undef STAGE
}

// ---------------- aggregation: fp16 gathers, fp32 accumulate -----------------
// x16 rows are pre-scaled by dinv: result = dinv_d*(sum x16[s] + x16[row]) + bias
// do_ln=1: LN+ReLU, write fp16 to out16. do_ln=0: write fp32 to outf.
__global__ void agg_kernel(const __half2* __restrict__ x16, float* __restrict__ outf,
                           __half2* __restrict__ out16,
                           const float* __restrict__ bias,
                           const float* __restrict__ lnw, const float* __restrict__ lnb,
                           int N, int do_ln) {
    int row = (blockIdx.x * blockDim.x + threadIdx.x) >> 5;
    int lane = threadIdx.x & 31;
    if (row >= N) return;
    int degr = g_degi[row];
    int deg = degr < MAXDEG ? degr : MAXDEG;
    const uint2* xr = (const uint2*)x16;   // [s*32 + lane] = 4 halves

    float4 acc = h4_to_f4(xr[(size_t)row * 32 + lane]);   // self term

    const int* ell = g_ell + (size_t)row * MAXDEG;
    int i = 0;
    for (; i + 4 <= deg; i += 4) {
        int s0 = ell[i], s1 = ell[i + 1], s2 = ell[i + 2], s3 = ell[i + 3];
        float4 v0 = h4_to_f4(xr[(size_t)s0 * 32 + lane]);
        float4 v1 = h4_to_f4(xr[(size_t)s1 * 32 + lane]);
        float4 v2 = h4_to_f4(xr[(size_t)s2 * 32 + lane]);
        float4 v3 = h4_to_f4(xr[(size_t)s3 * 32 + lane]);
        acc.x += v0.x + v1.x + v2.x + v3.x;
        acc.y += v0.y + v1.y + v2.y + v3.y;
        acc.z += v0.z + v1.z + v2.z + v3.z;
        acc.w += v0.w + v1.w + v2.w + v3.w;
    }
    for (; i < deg; i++) {
        int s0 = ell[i];
        float4 v0 = h4_to_f4(xr[(size_t)s0 * 32 + lane]);
        acc.x += v0.x;
        acc.y += v0.y;
        acc.z += v0.z;
        acc.w += v0.w;
    }

    float dinv_d = g_dinv[row];
    float4 bb = ((const float4*)bias)[lane];
    acc.x = acc.x * dinv_d + bb.x;
    acc.y = acc.y * dinv_d + bb.y;
    acc.z = acc.z * dinv_d + bb.z;
    acc.w = acc.w * dinv_d + bb.w;

    if (do_ln) {
        float s = acc.x + acc.y + acc.z + acc.w;
#pragma unroll
        for (int o = 16; o > 0; o >>= 1) s += __shfl_xor_sync(0xFFFFFFFFu, s, o);
        float mu = s * (1.0f / 128.0f);
        float dx = acc.x - mu, dy = acc.y - mu, dz = acc.z - mu, dw = acc.w - mu;
        float sq = dx * dx + dy * dy + dz * dz + dw * dw;
#pragma unroll
        for (int o = 16; o > 0; o >>= 1) sq += __shfl_xor_sync(0xFFFFFFFFu, sq, o);
        float rstd = rsqrtf(sq * (1.0f / 128.0f) + 1e-5f);
        float4 w = ((const float4*)lnw)[lane];
        float4 lb = ((const float4*)lnb)[lane];
        float ox = fmaxf(dx * rstd * w.x + lb.x, 0.0f);
        float oy = fmaxf(dy * rstd * w.y + lb.y, 0.0f);
        float oz = fmaxf(dz * rstd * w.z + lb.z, 0.0f);
        float ow = fmaxf(dw * rstd * w.w + lb.w, 0.0f);
        out16[(size_t)row * 64 + lane * 2]     = __floats2half2_rn(ox, oy);
        out16[(size_t)row * 64 + lane * 2 + 1] = __floats2half2_rn(oz, ow);
    } else {
        ((float4*)outf)[(size_t)row * C4 + lane] = acc;
    }
}

// ---------------- launcher ---------------------------------------------------
extern "C" void kernel_launch(void* const* d_in, const int* in_sizes, int n_in,
                              void* d_out, int out_size) {
    const float* h_noisy = (const float*)d_in[0];
    const int*   edge    = (const int*)  d_in[1];
    const float* t       = (const float*)d_in[2];
    const float* tW1     = (const float*)d_in[3];
    const float* tb1     = (const float*)d_in[4];
    const float* tW2     = (const float*)d_in[5];
    const float* tb2     = (const float*)d_in[6];
    const float* W1      = (const float*)d_in[7];
    const float* b1      = (const float*)d_in[8];
    const float* W2      = (const float*)d_in[9];
    const float* b2      = (const float*)d_in[10];
    const float* ln_w    = (const float*)d_in[11];
    const float* ln_b    = (const float*)d_in[12];
    float* out = (float*)d_out;

    int N = in_sizes[0] / C;
    int E = in_sizes[1] / 2;
    const int* src = edge;
    const int* dst = edge + E;

    __half2 *bufA16, *bufB16;
    uint2 *whi, *wlo;
    cudaGetSymbolAddress((void**)&bufA16, g_buf16a);
    cudaGetSymbolAddress((void**)&bufB16, g_buf16b);
    cudaGetSymbolAddress((void**)&whi, g_whi);
    cudaGetSymbolAddress((void**)&wlo, g_wlo);

    int nblkN = (N + 255) / 256;       // 391
    int nblkE = (E + 255) / 256;
    int ntiles = (N + BM - 1) / BM;    // 3125
    int row_blocks = (N * 32 + 255) / 256;

    // 1. fused setup (W pack + temb + deg init)
    setup_kernel<<<33 + nblkN, 256>>>(W1, W2, t, tW1, tb1, tW2, tb2, N);
    // 2. edge pass: degrees + ELL adjacency (one pass)
    fill_ell_kernel<<<nblkE, 256>>>(src, dst, E);
    // 3. dinv table
    dinv_kernel<<<nblkN, 256>>>(N);
    // 4. gemm1 (profiled slot): fp16( dinv * ((h + temb) @ W1) ) -> bufA16
    gemm_bf16_kernel<<<296, GEMM_THREADS>>>(h_noisy, whi, wlo, bufA16, N, ntiles, 1, 0);
    // 5. aggregate + LN + ReLU -> bufB16 (fp16)
    agg_kernel<<<row_blocks, 256>>>(bufA16, nullptr, bufB16, b1, ln_w, ln_b, N, 1);
    // 6. gemm2: fp16( dinv * (bufB16 @ W2) ) -> bufA16   (fp16 A, exact split)
    gemm_bf16_kernel<<<296, GEMM_THREADS>>>(bufB16, whi + 4096, wlo + 4096, bufA16, N, ntiles, 0, 1);
    // 7. aggregate -> out (fp32)
    agg_kernel<<<row_blocks, 256>>>(bufA16, out, nullptr, b2, nullptr, nullptr, N, 0);
}

// round 17
// speedup vs baseline: 1.2384x; 1.1323x over previous
#include <cuda_runtime.h>
#include <cuda_bf16.h>
#include <cuda_fp16.h>
#include <cstdint>

#define C 128
#define C4 32
#define MAX_N 100000
#define MAX_E 640000
#define MAXDEG 64
#define BM 32
#define GEMM_THREADS 256
#define A_SLAB 132                 // u32 per (k-chunk, mf) slab (128 + 4 pad)
#define A_U32 (16 * A_SLAB)        // 2112 u32 per buffer (single fp16 plane)

// ---------------- scratch (device globals) -----------------------------------
__device__ float g_temb[C];
__device__ int   g_degi[MAX_N];
__device__ float g_dinv[MAX_N];
__device__ int   g_ell[(size_t)MAX_N * MAXDEG];
__device__ __half2 g_buf16a[(size_t)MAX_N * 64];  // gemm outputs (pre-scaled)
__device__ __half2 g_buf16b[(size_t)MAX_N * 64];  // agg1 output (fp16)
__device__ uint2 g_whi[2][4096];   // fp16 W hi fragments
__device__ uint2 g_wlo[2][4096];   // fp16 W lo fragments

// ---------------- helpers ----------------------------------------------------
__device__ __forceinline__ unsigned pack_h2(float a, float b) {
    __half2 v = __floats2half2_rn(a, b);
    return *reinterpret_cast<unsigned*>(&v);
}
__device__ __forceinline__ float h_hi(float x) {
    return __half2float(__float2half_rn(x));
}
__device__ __forceinline__ float4 h4_to_f4(uint2 u) {
    __half2 a = *reinterpret_cast<__half2*>(&u.x);
    __half2 b = *reinterpret_cast<__half2*>(&u.y);
    float2 fa = __half22float2(a), fb = __half22float2(b);
    return make_float4(fa.x, fa.y, fb.x, fb.y);
}
__device__ __forceinline__ void mma16f(float* c, unsigned a0, unsigned a1,
                                       unsigned a2, unsigned a3,
                                       unsigned b0, unsigned b1) {
    asm volatile(
        "mma.sync.aligned.m16n8k16.row.col.f32.f16.f16.f32 "
        "{%0,%1,%2,%3}, {%4,%5,%6,%7}, {%8,%9}, {%0,%1,%2,%3};\n"
        : "+f"(c[0]), "+f"(c[1]), "+f"(c[2]), "+f"(c[3])
        : "r"(a0), "r"(a1), "r"(a2), "r"(a3), "r"(b0), "r"(b1));
}

// ---------------- fused setup: W pack (fp16 2-term) + temb + deg init --------
__global__ void setup_kernel(const float* __restrict__ W1, const float* __restrict__ W2,
                             const float* __restrict__ t,
                             const float* __restrict__ tW1, const float* __restrict__ tb1,
                             const float* __restrict__ tW2, const float* __restrict__ tb2,
                             int N) {
    int b = blockIdx.x;
    if (b < 32) {
        int id = b * 256 + threadIdx.x;   // 0..8191
        int mat = id >> 12;
        int rem = id & 4095;
        int ks = rem >> 9, nf = (rem >> 5) & 15, lane = rem & 31;
        int k0 = ks * 16 + (lane & 3) * 2;
        int n = nf * 8 + (lane >> 2);
        const float* W = mat ? W2 : W1;
        float v00 = W[k0 * C + n];
        float v01 = W[(k0 + 1) * C + n];
        float v10 = W[(k0 + 8) * C + n];
        float v11 = W[(k0 + 9) * C + n];
        float h00 = h_hi(v00), h01 = h_hi(v01), h10 = h_hi(v10), h11 = h_hi(v11);
        int idx = (ks * 16 + nf) * 32 + lane;
        g_whi[mat][idx] = make_uint2(pack_h2(h00, h01), pack_h2(h10, h11));
        g_wlo[mat][idx] = make_uint2(pack_h2(v00 - h00, v01 - h01),
                                     pack_h2(v10 - h10, v11 - h11));
    } else if (b == 32) {
        __shared__ float hid[C];
        int j = threadIdx.x;
        if (j < C) {
            float tv = t[0];
            hid[j] = fmaxf(tv * tW1[j] + tb1[j], 0.0f);
        }
        __syncthreads();
        if (j < C) {
            float s = tb2[j];
#pragma unroll 8
            for (int i = 0; i < C; i++) s += hid[i] * tW2[i * C + j];
            g_temb[j] = s;
        }
    } else {
        int i = (b - 33) * 256 + threadIdx.x;
        if (i < N) g_degi[i] = 0;
    }
}

// ---------------- edge pass: degree count + ELL fill (one pass) --------------
__global__ void fill_ell_kernel(const int* __restrict__ src, const int* __restrict__ dst,
                                int E) {
    int e = blockIdx.x * blockDim.x + threadIdx.x;
    if (e >= E) return;
    int d = dst[e];
    int slot = atomicAdd(&g_degi[d], 1);
    if (slot < MAXDEG)
        g_ell[(size_t)d * MAXDEG + slot] = src[e];
}

// ---------------- dinv table -------------------------------------------------
__global__ void dinv_kernel(int N) {
    int i = blockIdx.x * blockDim.x + threadIdx.x;
    if (i < N) g_dinv[i] = rsqrtf((float)g_degi[i] + 1.0f);
}

// ---------------- GEMM: out16 = fp16( dinv[row] * (A16 @ (Wh+Wl)) ) ----------
// A staged as fp16 (exact for fp16 input; 2^-12 rounding for fp32 input).
// 2-term fp16 MMA: D = A*Wh + A*Wl.
__global__ void __launch_bounds__(GEMM_THREADS, 2)
gemm_fp16_kernel(const void* __restrict__ Ain,
                 const uint2* __restrict__ whi, const uint2* __restrict__ wlo,
                 __half2* __restrict__ out16, int M, int ntiles,
                 int add_temb, int a_fp16) {
    __shared__ unsigned Ah[2][A_U32];
    int tid = threadIdx.x, lane = tid & 31, warpN = tid >> 5;   // warpN 0..7

    uint2 wh[8][2], wl[8][2];
#pragma unroll
    for (int ks = 0; ks < 8; ks++)
#pragma unroll
        for (int j = 0; j < 2; j++) {
            int idx = (ks * 16 + warpN * 2 + j) * 32 + lane;
            wh[ks][j] = whi[idx];
            wl[ks][j] = wlo[idx];
        }

    int c4 = tid & 31;
    int ks_t = c4 >> 2;
    int khigh = (c4 >> 1) & 1;
    int kp0 = (c4 & 1) * 2;
    float4 tmb = make_float4(0.f, 0.f, 0.f, 0.f);
    if (add_temb) tmb = ((const float4*)g_temb)[c4];

    const float4* Af = (const float4*)Ain;
    const uint2* Ah16 = (const uint2*)Ain;

    int G = gridDim.x;
    int tile = blockIdx.x;
    float4 pf[4];

#define LOADPF(T)                                                              \
    {                                                                          \
        _Pragma("unroll") for (int i = 0; i < 4; i++) {                        \
            int row = (T) * BM + warpN + i * 8;                                \
            if (row < M) {                                                     \
                pf[i] = a_fp16 ? h4_to_f4(Ah16[(size_t)row * 32 + c4])         \
                               : Af[(size_t)row * C4 + c4];                    \
            } else {                                                           \
                pf[i] = make_float4(0.f, 0.f, 0.f, 0.f);                       \
            }                                                                  \
        }                                                                      \
    }

#define STAGE(S)                                                               \
    {                                                                          \
        _Pragma("unroll") for (int i = 0; i < 4; i++) {                        \
            int r = warpN + i * 8;                                             \
            int rloc = r & 15, mf = r >> 4;                                    \
            float4 v = pf[i];                                                  \
            v.x += tmb.x; v.y += tmb.y; v.z += tmb.z; v.w += tmb.w;            \
            int slot = (ks_t * 2 + mf) * A_SLAB + ((rloc & 7) * 4 + kp0) * 4   \
                       + (rloc >> 3) + 2 * khigh;                              \
            Ah[S][slot]     = pack_h2(v.x, v.y);                               \
            Ah[S][slot + 4] = pack_h2(v.z, v.w);                               \
        }                                                                      \
    }

    if (tile < ntiles) {
        LOADPF(tile);
        STAGE(0);
        if (tile + G < ntiles) LOADPF(tile + G);
    }
    int s = 0;

    while (tile < ntiles) {
        __syncthreads();   // buf[s] staging complete across all warps
        if (tile + G < ntiles) {
            STAGE(s ^ 1);
            if (tile + 2 * G < ntiles) LOADPF(tile + 2 * G);
        }

        // hoist epilogue dinv loads so they're in flight during the MMA loop
        int eg = lane >> 2, ecc = lane & 3;
        float sd[2][2];
#pragma unroll
        for (int mf = 0; mf < 2; mf++) {
            int row0 = tile * BM + mf * 16 + eg;
            sd[mf][0] = (row0 < M) ? g_dinv[row0] : 0.f;
            sd[mf][1] = (row0 + 8 < M) ? g_dinv[row0 + 8] : 0.f;
        }

        float acc[2][2][4];
#pragma unroll
        for (int mf = 0; mf < 2; mf++)
#pragma unroll
            for (int j = 0; j < 2; j++)
#pragma unroll
                for (int x = 0; x < 4; x++) acc[mf][j][x] = 0.f;

        const uint4* Ah4 = (const uint4*)Ah[s];
#pragma unroll
        for (int ks = 0; ks < 8; ks++) {
#pragma unroll
            for (int mf = 0; mf < 2; mf++) {
                uint4 ah = Ah4[(ks * 2 + mf) * (A_SLAB / 4) + lane];
#pragma unroll
                for (int j = 0; j < 2; j++) {
                    mma16f(acc[mf][j], ah.x, ah.y, ah.z, ah.w, wh[ks][j].x, wh[ks][j].y);
                    mma16f(acc[mf][j], ah.x, ah.y, ah.z, ah.w, wl[ks][j].x, wl[ks][j].y);
                }
            }
        }

        // epilogue: scale by pre-loaded dinv, convert to fp16, store half2
        {
#pragma unroll
            for (int mf = 0; mf < 2; mf++) {
                int row0 = tile * BM + mf * 16 + eg;
#pragma unroll
                for (int j = 0; j < 2; j++) {
                    int col2 = ((warpN * 2 + j) * 8 + ecc * 2) >> 1;  // half2 index
                    if (row0 < M)
                        out16[(size_t)row0 * 64 + col2] =
                            __floats2half2_rn(acc[mf][j][0] * sd[mf][0],
                                              acc[mf][j][1] * sd[mf][0]);
                    if (row0 + 8 < M)
                        out16[(size_t)(row0 + 8) * 64 + col2] =
                            __floats2half2_rn(acc[mf][j][2] * sd[mf][1],
                                              acc[mf][j][3] * sd[mf][1]);
                }
            }
        }
        s ^= 1;
        tile += G;
    }
#undef LOADPF
#undef STAGE
}

// ---------------- aggregation: fp16 gathers, fp32 accumulate -----------------
// x16 rows are pre-scaled by dinv: result = dinv_d*(sum x16[s] + x16[row]) + bias
// do_ln=1: LN+ReLU, write fp16 to out16. do_ln=0: write fp32 to outf.
__global__ void agg_kernel(const __half2* __restrict__ x16, float* __restrict__ outf,
                           __half2* __restrict__ out16,
                           const float* __restrict__ bias,
                           const float* __restrict__ lnw, const float* __restrict__ lnb,
                           int N, int do_ln) {
    int row = (blockIdx.x * blockDim.x + threadIdx.x) >> 5;
    int lane = threadIdx.x & 31;
    if (row >= N) return;
    int degr = g_degi[row];
    int deg = degr < MAXDEG ? degr : MAXDEG;
    const uint2* xr = (const uint2*)x16;   // [s*32 + lane] = 4 halves

    float4 acc = h4_to_f4(xr[(size_t)row * 32 + lane]);   // self term

    const int* ell = g_ell + (size_t)row * MAXDEG;
    int i = 0;
    for (; i + 4 <= deg; i += 4) {
        int s0 = ell[i], s1 = ell[i + 1], s2 = ell[i + 2], s3 = ell[i + 3];
        float4 v0 = h4_to_f4(xr[(size_t)s0 * 32 + lane]);
        float4 v1 = h4_to_f4(xr[(size_t)s1 * 32 + lane]);
        float4 v2 = h4_to_f4(xr[(size_t)s2 * 32 + lane]);
        float4 v3 = h4_to_f4(xr[(size_t)s3 * 32 + lane]);
        acc.x += v0.x + v1.x + v2.x + v3.x;
        acc.y += v0.y + v1.y + v2.y + v3.y;
        acc.z += v0.z + v1.z + v2.z + v3.z;
        acc.w += v0.w + v1.w + v2.w + v3.w;
    }
    for (; i < deg; i++) {
        int s0 = ell[i];
        float4 v0 = h4_to_f4(xr[(size_t)s0 * 32 + lane]);
        acc.x += v0.x;
        acc.y += v0.y;
        acc.z += v0.z;
        acc.w += v0.w;
    }

    float dinv_d = g_dinv[row];
    float4 bb = ((const float4*)bias)[lane];
    acc.x = acc.x * dinv_d + bb.x;
    acc.y = acc.y * dinv_d + bb.y;
    acc.z = acc.z * dinv_d + bb.z;
    acc.w = acc.w * dinv_d + bb.w;

    if (do_ln) {
        float s = acc.x + acc.y + acc.z + acc.w;
#pragma unroll
        for (int o = 16; o > 0; o >>= 1) s += __shfl_xor_sync(0xFFFFFFFFu, s, o);
        float mu = s * (1.0f / 128.0f);
        float dx = acc.x - mu, dy = acc.y - mu, dz = acc.z - mu, dw = acc.w - mu;
        float sq = dx * dx + dy * dy + dz * dz + dw * dw;
#pragma unroll
        for (int o = 16; o > 0; o >>= 1) sq += __shfl_xor_sync(0xFFFFFFFFu, sq, o);
        float rstd = rsqrtf(sq * (1.0f / 128.0f) + 1e-5f);
        float4 w = ((const float4*)lnw)[lane];
        float4 lb = ((const float4*)lnb)[lane];
        float ox = fmaxf(dx * rstd * w.x + lb.x, 0.0f);
        float oy = fmaxf(dy * rstd * w.y + lb.y, 0.0f);
        float oz = fmaxf(dz * rstd * w.z + lb.z, 0.0f);
        float ow = fmaxf(dw * rstd * w.w + lb.w, 0.0f);
        out16[(size_t)row * 64 + lane * 2]     = __floats2half2_rn(ox, oy);
        out16[(size_t)row * 64 + lane * 2 + 1] = __floats2half2_rn(oz, ow);
    } else {
        ((float4*)outf)[(size_t)row * C4 + lane] = acc;
    }
}

// ---------------- launcher ---------------------------------------------------
extern "C" void kernel_launch(void* const* d_in, const int* in_sizes, int n_in,
                              void* d_out, int out_size) {
    const float* h_noisy = (const float*)d_in[0];
    const int*   edge    = (const int*)  d_in[1];
    const float* t       = (const float*)d_in[2];
    const float* tW1     = (const float*)d_in[3];
    const float* tb1     = (const float*)d_in[4];
    const float* tW2     = (const float*)d_in[5];
    const float* tb2     = (const float*)d_in[6];
    const float* W1      = (const float*)d_in[7];
    const float* b1      = (const float*)d_in[8];
    const float* W2      = (const float*)d_in[9];
    const float* b2      = (const float*)d_in[10];
    const float* ln_w    = (const float*)d_in[11];
    const float* ln_b    = (const float*)d_in[12];
    float* out = (float*)d_out;

    int N = in_sizes[0] / C;
    int E = in_sizes[1] / 2;
    const int* src = edge;
    const int* dst = edge + E;

    __half2 *bufA16, *bufB16;
    uint2 *whi, *wlo;
    cudaGetSymbolAddress((void**)&bufA16, g_buf16a);
    cudaGetSymbolAddress((void**)&bufB16, g_buf16b);
    cudaGetSymbolAddress((void**)&whi, g_whi);
    cudaGetSymbolAddress((void**)&wlo, g_wlo);

    int nblkN = (N + 255) / 256;       // 391
    int nblkE = (E + 255) / 256;
    int ntiles = (N + BM - 1) / BM;    // 3125
    int row_blocks = (N * 32 + 255) / 256;

    // 1. fused setup (W fp16 2-term pack + temb + deg init)
    setup_kernel<<<33 + nblkN, 256>>>(W1, W2, t, tW1, tb1, tW2, tb2, N);
    // 2. edge pass: degrees + ELL adjacency (one pass)
    fill_ell_kernel<<<nblkE, 256>>>(src, dst, E);
    // 3. dinv table
    dinv_kernel<<<nblkN, 256>>>(N);
    // 4. gemm1 (profiled slot): fp16( dinv * ((h + temb) @ W1) ) -> bufA16
    gemm_fp16_kernel<<<296, GEMM_THREADS>>>(h_noisy, whi, wlo, bufA16, N, ntiles, 1, 0);
    // 5. aggregate + LN + ReLU -> bufB16 (fp16)
    agg_kernel<<<row_blocks, 256>>>(bufA16, nullptr, bufB16, b1, ln_w, ln_b, N, 1);
    // 6. gemm2: fp16( dinv * (bufB16 @ W2) ) -> bufA16
    gemm_fp16_kernel<<<296, GEMM_THREADS>>>(bufB16, whi + 4096, wlo + 4096, bufA16, N, ntiles, 0, 1);
    // 7. aggregate -> out (fp32)
    agg_kernel<<<row_blocks, 256>>>(bufA16, out, nullptr, b2, nullptr, nullptr, N, 0);
}